// round 1
// baseline (speedup 1.0000x reference)
#include <cuda_runtime.h>
#include <cuda_bf16.h>
#include <mma.h>

using namespace nvcuda;

#define B_    16
#define N_    1024
#define M_    1024
#define D_    512
#define NDIAG 2047            // theta anti-diagonals: i+j in [0, 2046]
#define LOG2E 1.4426950408889634f
#define LN2   0.6931471805599453f
#define NEGW  -1.0e9f

// ---------------- device scratch (static globals: no allocation) ----------------
__device__ __nv_bfloat16 g_zx[(size_t)B_ * N_ * D_];
__device__ __nv_bfloat16 g_zy[(size_t)B_ * M_ * D_];
__device__ float g_theta[(size_t)B_ * NDIAG * 1024];   // diag-major: [b][d][i], ~134MB
__device__ float g_A[B_];

// ---------------- fast MUFU intrinsics ----------------
__device__ __forceinline__ float ex2f_(float x) {
    float y; asm("ex2.approx.ftz.f32 %0, %1;" : "=f"(y) : "f"(x)); return y;
}
__device__ __forceinline__ float lg2f_(float x) {
    float y; asm("lg2.approx.ftz.f32 %0, %1;" : "=f"(y) : "f"(x)); return y;
}

// ---------------- 1) fp32 -> bf16 conversion ----------------
__global__ void convert_kernel(const float* __restrict__ x, const float* __restrict__ y) {
    int i = blockIdx.x * blockDim.x + threadIdx.x;
    int st = gridDim.x * blockDim.x;
    const int n = B_ * N_ * D_;
    for (; i < n; i += st) {
        g_zx[i] = __float2bfloat16(x[i]);
        g_zy[i] = __float2bfloat16(y[i]);
    }
}

// ---------------- 2) gap score A[b] (deterministic block reduce) ----------------
__global__ void __launch_bounds__(1024) gap_kernel(const float* __restrict__ zx,
                                                   const float* __restrict__ zy,
                                                   const float* __restrict__ gw,
                                                   const float* __restrict__ gb) {
    int b = blockIdx.x;
    int tid = threadIdx.x;          // 1024 threads
    int c = tid & 511;              // feature dim
    int half = tid >> 9;            // rows [half*512, half*512+512)
    const float* px = zx + ((size_t)b * N_ + (size_t)half * 512) * D_ + c;
    const float* py = zy + ((size_t)b * M_ + (size_t)half * 512) * D_ + c;
    float sx = 0.f, sy = 0.f;
#pragma unroll 4
    for (int i = 0; i < 512; i++) {
        sx += px[(size_t)i * D_];
        sy += py[(size_t)i * D_];
    }
    float v = sx * (1.0f / N_) * gw[c] + sy * (1.0f / M_) * gw[512 + c];
    __shared__ float red[1024];
    red[tid] = v;
    __syncthreads();
    for (int s = 512; s > 0; s >>= 1) {
        if (tid < s) red[tid] += red[tid + s];
        __syncthreads();
    }
    if (tid == 0) g_A[b] = (red[0] + gb[0]) * LOG2E;   // log2-domain gap
}

// ---------------- 3) GEMM theta = zx @ zy^T, bf16 WMMA, diag-layout epilogue ----------------
// block tile 128x128, 8 warps (4 row x 2 col), each warp 32x64.
__global__ void __launch_bounds__(256) gemm_kernel() {
    int b  = blockIdx.z;
    int I0 = blockIdx.y * 128;
    int J0 = blockIdx.x * 128;
    const __nv_bfloat16* Ab = g_zx + (size_t)b * N_ * D_;
    const __nv_bfloat16* Bb = g_zy + (size_t)b * M_ * D_;

    int warpId = threadIdx.x >> 5;
    int wr = warpId & 3;       // 0..3 (rows of 32)
    int wc = warpId >> 2;      // 0..1 (cols of 64)

    wmma::fragment<wmma::accumulator, 16, 16, 16, float> acc[2][4];
#pragma unroll
    for (int i = 0; i < 2; i++)
#pragma unroll
        for (int j = 0; j < 4; j++) wmma::fill_fragment(acc[i][j], 0.0f);

    wmma::fragment<wmma::matrix_a, 16, 16, 16, __nv_bfloat16, wmma::row_major> af[2];
    wmma::fragment<wmma::matrix_b, 16, 16, 16, __nv_bfloat16, wmma::col_major> bfr[4];

    for (int k0 = 0; k0 < D_; k0 += 16) {
#pragma unroll
        for (int i = 0; i < 2; i++)
            wmma::load_matrix_sync(af[i], Ab + (size_t)(I0 + wr * 32 + i * 16) * D_ + k0, D_);
#pragma unroll
        for (int j = 0; j < 4; j++)
            wmma::load_matrix_sync(bfr[j], Bb + (size_t)(J0 + wc * 64 + j * 16) * D_ + k0, D_);
#pragma unroll
        for (int i = 0; i < 2; i++)
#pragma unroll
            for (int j = 0; j < 4; j++)
                wmma::mma_sync(acc[i][j], af[i], bfr[j], acc[i][j]);
    }

    // Epilogue: stage 64x128 halves in smem, drain in anti-diagonal order (coalesced STG).
    __shared__ float tile[64 * 128];
    for (int phase = 0; phase < 2; phase++) {
        if ((wr >> 1) == phase) {
            int lr = (wr & 1) * 32;
#pragma unroll
            for (int i = 0; i < 2; i++)
#pragma unroll
                for (int j = 0; j < 4; j++)
                    wmma::store_matrix_sync(tile + (size_t)(lr + i * 16) * 128 + wc * 64 + j * 16,
                                            acc[i][j], 128, wmma::mem_row_major);
        }
        __syncthreads();
        int rowoff = phase * 64;
        for (int e = threadIdx.x; e < 191 * 64; e += 256) {
            int dl = e >> 6;                          // local diag 0..190
            int t  = e & 63;
            int li = (dl > 127 ? dl - 127 : 0) + t;   // local row in half-tile
            int lj = dl - li;
            if (li < 64 && lj >= 0 && lj < 128) {
                int gi = I0 + rowoff + li;
                int gj = J0 + lj;
                // log2-domain theta
                g_theta[((size_t)b * NDIAG + (gi + gj)) * 1024 + gi] = tile[li * 128 + lj] * LOG2E;
            }
        }
        __syncthreads();
    }
}

// ---------------- 4) wavefront DP (log2 domain), one CTA per batch ----------------
__global__ void __launch_bounds__(1024) dp_kernel(float* __restrict__ out) {
    int b = blockIdx.x;
    int t = threadIdx.x;              // theta row i = t, V row r = t+1
    __shared__ float buf[3][1028];

    // buf[0] = V diag 0 (index0 = V[0,0] = 0), buf[1] = V diag 1 (all NEG)
    buf[0][t] = (t == 0) ? 0.0f : NEGW;
    buf[1][t] = NEGW;
    buf[2][t] = NEGW;
    if (t == 0) { buf[0][1024] = NEGW; buf[1][1024] = NEGW; buf[2][1024] = NEGW; }
    __syncthreads();

    const float A = g_A[b];           // already * log2e
    const float* th = g_theta + (size_t)b * NDIAG * 1024;

    float thv = th[t];                // theta for d=0 (prefetched)
    int ip2 = 0, ip1 = 1, ic = 2;

    for (int d = 0; d < NDIAG; d++) {
        float th_next = (d + 1 < NDIAG) ? th[(size_t)(d + 1) * 1024 + t] : 0.0f;

        float up = buf[ip1][t] + A;        // V[r-1, c] + A
        float dg = buf[ip2][t];            // V[r-1, c-1]
        float lf = buf[ip1][t + 1] + A;    // V[r, c-1] + A

        float m  = fmaxf(up, fmaxf(dg, lf));
        float lo = fminf(up, fminf(dg, lf));
        float mid = ((up + dg) + lf - m) - lo;
        float s = 1.0f + ex2f_(lo - m) + ex2f_(mid - m);   // max term = 2^0 = 1
        float val = thv + m + lg2f_(s);

        bool valid = (unsigned)(d - t) <= 1023u;           // j = d - i in range
        buf[ic][t + 1] = valid ? val : NEGW;
        if (t == 0) buf[ic][0] = NEGW;
        __syncthreads();

        thv = th_next;
        int tmp = ip2; ip2 = ip1; ip1 = ic; ic = tmp;
    }
    if (t == 1023) out[b] = buf[ip1][1024] * LN2;          // V[N, M]
}

// ---------------- launch ----------------
extern "C" void kernel_launch(void* const* d_in, const int* in_sizes, int n_in,
                              void* d_out, int out_size) {
    (void)in_sizes; (void)n_in; (void)out_size;
    const float* zx = (const float*)d_in[0];
    const float* zy = (const float*)d_in[1];
    const float* gw = (const float*)d_in[2];
    const float* gb = (const float*)d_in[3];
    float* out = (float*)d_out;

    convert_kernel<<<1024, 256>>>(zx, zy);
    gap_kernel<<<B_, 1024>>>(zx, zy, gw, gb);
    gemm_kernel<<<dim3(8, 8, B_), 256>>>();
    dp_kernel<<<B_, 1024>>>(out);
}

// round 2
// speedup vs baseline: 1.4996x; 1.4996x over previous
#include <cuda_runtime.h>
#include <cuda_bf16.h>
#include <mma.h>

using namespace nvcuda;

#define B_    16
#define N_    1024
#define M_    1024
#define D_    512
#define NDIAG 2047            // theta anti-diagonals: i+j in [0, 2046]
#define LOG2E 1.4426950408889634f
#define LN2   0.6931471805599453f
#define NEGW  -1.0e9f

// ---------------- device scratch (static globals: no allocation) ----------------
__device__ __nv_bfloat16 g_zx[(size_t)B_ * N_ * D_];
__device__ __nv_bfloat16 g_zy[(size_t)B_ * M_ * D_];
// diag-major: [b][d][i], ~134MB, +4 diagonals of pad so prefetch never reads OOB
__device__ float g_theta[(size_t)B_ * NDIAG * 1024 + 4 * 1024];
__device__ float g_A[B_];

// ---------------- fast MUFU intrinsics ----------------
__device__ __forceinline__ float ex2f_(float x) {
    float y; asm("ex2.approx.ftz.f32 %0, %1;" : "=f"(y) : "f"(x)); return y;
}
__device__ __forceinline__ float lg2f_(float x) {
    float y; asm("lg2.approx.ftz.f32 %0, %1;" : "=f"(y) : "f"(x)); return y;
}

// ---------------- 1) fp32 -> bf16 conversion ----------------
__global__ void convert_kernel(const float* __restrict__ x, const float* __restrict__ y) {
    int i = blockIdx.x * blockDim.x + threadIdx.x;
    int st = gridDim.x * blockDim.x;
    const int n = B_ * N_ * D_;
    for (; i < n; i += st) {
        g_zx[i] = __float2bfloat16(x[i]);
        g_zy[i] = __float2bfloat16(y[i]);
    }
}

// ---------------- 2) gap score A[b] (deterministic block reduce) ----------------
__global__ void __launch_bounds__(1024) gap_kernel(const float* __restrict__ zx,
                                                   const float* __restrict__ zy,
                                                   const float* __restrict__ gw,
                                                   const float* __restrict__ gb) {
    int b = blockIdx.x;
    int tid = threadIdx.x;          // 1024 threads
    int c = tid & 511;              // feature dim
    int half = tid >> 9;            // rows [half*512, half*512+512)
    const float* px = zx + ((size_t)b * N_ + (size_t)half * 512) * D_ + c;
    const float* py = zy + ((size_t)b * M_ + (size_t)half * 512) * D_ + c;
    float sx = 0.f, sy = 0.f;
#pragma unroll 4
    for (int i = 0; i < 512; i++) {
        sx += px[(size_t)i * D_];
        sy += py[(size_t)i * D_];
    }
    float v = sx * (1.0f / N_) * gw[c] + sy * (1.0f / M_) * gw[512 + c];
    __shared__ float red[1024];
    red[tid] = v;
    __syncthreads();
    for (int s = 512; s > 0; s >>= 1) {
        if (tid < s) red[tid] += red[tid + s];
        __syncthreads();
    }
    if (tid == 0) g_A[b] = (red[0] + gb[0]) * LOG2E;   // log2-domain gap
}

// ---------------- 3) GEMM theta = zx @ zy^T, bf16 WMMA, diag-layout epilogue ----------------
// block tile 128x128, 8 warps (4 row x 2 col), each warp 32x64.
__global__ void __launch_bounds__(256) gemm_kernel() {
    int b  = blockIdx.z;
    int I0 = blockIdx.y * 128;
    int J0 = blockIdx.x * 128;
    const __nv_bfloat16* Ab = g_zx + (size_t)b * N_ * D_;
    const __nv_bfloat16* Bb = g_zy + (size_t)b * M_ * D_;

    int warpId = threadIdx.x >> 5;
    int wr = warpId & 3;       // 0..3 (rows of 32)
    int wc = warpId >> 2;      // 0..1 (cols of 64)

    wmma::fragment<wmma::accumulator, 16, 16, 16, float> acc[2][4];
#pragma unroll
    for (int i = 0; i < 2; i++)
#pragma unroll
        for (int j = 0; j < 4; j++) wmma::fill_fragment(acc[i][j], 0.0f);

    wmma::fragment<wmma::matrix_a, 16, 16, 16, __nv_bfloat16, wmma::row_major> af[2];
    wmma::fragment<wmma::matrix_b, 16, 16, 16, __nv_bfloat16, wmma::col_major> bfr[4];

    for (int k0 = 0; k0 < D_; k0 += 16) {
#pragma unroll
        for (int i = 0; i < 2; i++)
            wmma::load_matrix_sync(af[i], Ab + (size_t)(I0 + wr * 32 + i * 16) * D_ + k0, D_);
#pragma unroll
        for (int j = 0; j < 4; j++)
            wmma::load_matrix_sync(bfr[j], Bb + (size_t)(J0 + wc * 64 + j * 16) * D_ + k0, D_);
#pragma unroll
        for (int i = 0; i < 2; i++)
#pragma unroll
            for (int j = 0; j < 4; j++)
                wmma::mma_sync(acc[i][j], af[i], bfr[j], acc[i][j]);
    }

    // Epilogue: stage 64x128 halves in smem, drain in anti-diagonal order (coalesced STG).
    __shared__ float tile[64 * 128];
    for (int phase = 0; phase < 2; phase++) {
        if ((wr >> 1) == phase) {
            int lr = (wr & 1) * 32;
#pragma unroll
            for (int i = 0; i < 2; i++)
#pragma unroll
                for (int j = 0; j < 4; j++)
                    wmma::store_matrix_sync(tile + (size_t)(lr + i * 16) * 128 + wc * 64 + j * 16,
                                            acc[i][j], 128, wmma::mem_row_major);
        }
        __syncthreads();
        int rowoff = phase * 64;
        for (int e = threadIdx.x; e < 191 * 64; e += 256) {
            int dl = e >> 6;                          // local diag 0..190
            int t  = e & 63;
            int li = (dl > 127 ? dl - 127 : 0) + t;   // local row in half-tile
            int lj = dl - li;
            if (li < 64 && lj >= 0 && lj < 128) {
                int gi = I0 + rowoff + li;
                int gj = J0 + lj;
                // log2-domain theta
                g_theta[((size_t)b * NDIAG + (gi + gj)) * 1024 + gi] = tile[li * 128 + lj] * LOG2E;
            }
        }
        __syncthreads();
    }
}

// ---------------- 4) wavefront DP (log2 domain), one CTA per batch ----------------
// Register-carried recurrence: per diagonal each thread does 1 LDS + 1 STS + 3 MUFU.
// Theta is prefetched 4 diagonals ahead (register ring) to hide DRAM latency.
__global__ void __launch_bounds__(1024) dp_kernel(float* __restrict__ out) {
    int b = blockIdx.x;
    int t = threadIdx.x;              // theta row i = t, V row r = t+1
    __shared__ float sbuf[2][1032];   // slot 0 = V row-0 boundary (always NEG, never written)

    sbuf[0][t + 1] = NEGW;
    sbuf[1][t + 1] = NEGW;            // "V diag 1" values (all NEG)
    if (t == 0) { sbuf[0][0] = NEGW; sbuf[1][0] = NEGW; }
    __syncthreads();

    const float A  = g_A[b];          // already * log2e
    const float A2 = A + A;
    const float* thp = g_theta + (size_t)b * NDIAG * 1024 + t;

    // register state
    float nb_prev = (t == 0) ? 0.0f : NEGW;  // neighbor (t-1) value @ diag d-2; init = V diag 0
    float my_prev = NEGW;                    // my value @ diag d-1;            init = V diag 1
    int   cur = 0;

    // 4-deep theta prefetch ring
    float thb0 = thp[0];
    float thb1 = thp[1024];
    float thb2 = thp[2 * 1024];
    float thb3 = thp[3 * 1024];
    const float* pf = thp + 4 * 1024;  // next address to prefetch

#define DP_STEP(THV, DD, DO_PF)                                            \
    {                                                                      \
        float nb = sbuf[cur ^ 1][t];                                       \
        float pre = DO_PF ? *pf : 0.0f;                                    \
        if (DO_PF) pf += 1024;                                             \
        float h  = fmaxf(nb, my_prev);                                     \
        float l  = fminf(nb, my_prev);                                     \
        float m  = fmaxf(h + A, nb_prev);                                  \
        float lo = fminf(l + A, nb_prev);                                  \
        float mid = ((h + l) + A2) + (nb_prev - m) - lo;                   \
        float s  = 1.0f + ex2f_(lo - m) + ex2f_(mid - m);                  \
        float val = (THV + m) + lg2f_(s);                                  \
        bool valid = ((unsigned)((DD) - t)) <= 1023u;                      \
        val = valid ? val : NEGW;                                          \
        nb_prev = nb;                                                      \
        my_prev = val;                                                     \
        sbuf[cur][t + 1] = val;                                            \
        __syncthreads();                                                   \
        cur ^= 1;                                                          \
        (THV) = pre;                                                       \
    }

    // main loop: 511 * 4 = 2044 diagonals (prefetch reads stay inside the 4-diag pad)
    for (int d = 0; d < 2044; d += 4) {
        DP_STEP(thb0, d + 0, 1)
        DP_STEP(thb1, d + 1, 1)
        DP_STEP(thb2, d + 2, 1)
        DP_STEP(thb3, d + 3, 1)
    }
    // tail: diagonals 2044, 2045, 2046 (already resident in thb0..thb2)
    DP_STEP(thb0, 2044, 0)
    DP_STEP(thb1, 2045, 0)
    DP_STEP(thb2, 2046, 0)
#undef DP_STEP

    // V[N, M] = value computed by thread 1023 at diag 2046 (r=1024, c=1024)
    if (t == 1023) out[b] = my_prev * LN2;
}

// ---------------- launch ----------------
extern "C" void kernel_launch(void* const* d_in, const int* in_sizes, int n_in,
                              void* d_out, int out_size) {
    (void)in_sizes; (void)n_in; (void)out_size;
    const float* zx = (const float*)d_in[0];
    const float* zy = (const float*)d_in[1];
    const float* gw = (const float*)d_in[2];
    const float* gb = (const float*)d_in[3];
    float* out = (float*)d_out;

    convert_kernel<<<1024, 256>>>(zx, zy);
    gap_kernel<<<B_, 1024>>>(zx, zy, gw, gb);
    gemm_kernel<<<dim3(8, 8, B_), 256>>>();
    dp_kernel<<<B_, 1024>>>(out);
}

// round 3
// speedup vs baseline: 1.5168x; 1.0115x over previous
#include <cuda_runtime.h>
#include <cuda_bf16.h>
#include <mma.h>

using namespace nvcuda;

#define B_    16
#define N_    1024
#define M_    1024
#define D_    512
#define NDIAG 2047            // theta anti-diagonals: i+j in [0, 2046]
#define LOG2E 1.4426950408889634f
#define LN2   0.6931471805599453f
#define NEGW  -1.0e9f
#define STRIPS 8
#define SROWS  128

// ---------------- device scratch (static globals: no allocation) ----------------
__device__ __nv_bfloat16 g_zx[(size_t)B_ * N_ * D_];
__device__ __nv_bfloat16 g_zy[(size_t)B_ * M_ * D_];
// diag-major: [b][d][i], ~134MB, +8 diagonals of pad so prefetch never reads OOB
__device__ float g_theta[(size_t)B_ * NDIAG * 1024 + 8 * 1024];
__device__ float g_A[B_];
__device__ float g_bound[B_][STRIPS][2048];   // strip boundary V-row values by global diag
__device__ int   g_prog[B_][STRIPS];          // release/acquire progress per strip

// ---------------- fast MUFU intrinsics ----------------
__device__ __forceinline__ float ex2f_(float x) {
    float y; asm("ex2.approx.ftz.f32 %0, %1;" : "=f"(y) : "f"(x)); return y;
}
__device__ __forceinline__ float lg2f_(float x) {
    float y; asm("lg2.approx.ftz.f32 %0, %1;" : "=f"(y) : "f"(x)); return y;
}
__device__ __forceinline__ int ld_acq(const int* p) {
    int v; asm volatile("ld.acquire.gpu.global.b32 %0, [%1];" : "=r"(v) : "l"(p)); return v;
}
__device__ __forceinline__ void st_rel(int* p, int v) {
    asm volatile("st.release.gpu.global.b32 [%0], %1;" :: "l"(p), "r"(v));
}

// ---------------- 0) reset progress flags (graph-replay safe) ----------------
__global__ void reset_kernel() {
    int i = threadIdx.x;
    if (i < B_ * STRIPS) ((int*)g_prog)[i] = -1;
}

// ---------------- 1) fp32 -> bf16 conversion ----------------
__global__ void convert_kernel(const float* __restrict__ x, const float* __restrict__ y) {
    int i = blockIdx.x * blockDim.x + threadIdx.x;
    int st = gridDim.x * blockDim.x;
    const int n = B_ * N_ * D_;
    for (; i < n; i += st) {
        g_zx[i] = __float2bfloat16(x[i]);
        g_zy[i] = __float2bfloat16(y[i]);
    }
}

// ---------------- 2) gap score A[b] (deterministic block reduce) ----------------
__global__ void __launch_bounds__(1024) gap_kernel(const float* __restrict__ zx,
                                                   const float* __restrict__ zy,
                                                   const float* __restrict__ gw,
                                                   const float* __restrict__ gb) {
    int b = blockIdx.x;
    int tid = threadIdx.x;          // 1024 threads
    int c = tid & 511;              // feature dim
    int half = tid >> 9;            // rows [half*512, half*512+512)
    const float* px = zx + ((size_t)b * N_ + (size_t)half * 512) * D_ + c;
    const float* py = zy + ((size_t)b * M_ + (size_t)half * 512) * D_ + c;
    float sx = 0.f, sy = 0.f;
#pragma unroll 4
    for (int i = 0; i < 512; i++) {
        sx += px[(size_t)i * D_];
        sy += py[(size_t)i * D_];
    }
    float v = sx * (1.0f / N_) * gw[c] + sy * (1.0f / M_) * gw[512 + c];
    __shared__ float red[1024];
    red[tid] = v;
    __syncthreads();
    for (int s = 512; s > 0; s >>= 1) {
        if (tid < s) red[tid] += red[tid + s];
        __syncthreads();
    }
    if (tid == 0) g_A[b] = (red[0] + gb[0]) * LOG2E;   // log2-domain gap
}

// ---------------- 3) GEMM theta = zx @ zy^T, bf16 WMMA with smem staging ----------------
// block tile 128x128, 8 warps (4 row x 2 col), each warp 32x64. K staged in 64-chunks.
__global__ void __launch_bounds__(256) gemm_kernel() {
    __shared__ __align__(16) __nv_bfloat16 sm[2][128 * 72];   // A | B, 36.9KB (pad 72)

    int b  = blockIdx.z;
    int I0 = blockIdx.y * 128;
    int J0 = blockIdx.x * 128;
    const __nv_bfloat16* Ag = g_zx + ((size_t)b * N_ + I0) * D_;
    const __nv_bfloat16* Bg = g_zy + ((size_t)b * M_ + J0) * D_;

    int warpId = threadIdx.x >> 5;
    int wr = warpId & 3;       // 0..3 (rows of 32)
    int wc = warpId >> 2;      // 0..1 (cols of 64)

    wmma::fragment<wmma::accumulator, 16, 16, 16, float> acc[2][4];
#pragma unroll
    for (int i = 0; i < 2; i++)
#pragma unroll
        for (int j = 0; j < 4; j++) wmma::fill_fragment(acc[i][j], 0.0f);

    wmma::fragment<wmma::matrix_a, 16, 16, 16, __nv_bfloat16, wmma::row_major> af[2];
    wmma::fragment<wmma::matrix_b, 16, 16, 16, __nv_bfloat16, wmma::col_major> bfr[4];

    int lr  = threadIdx.x >> 3;      // 0..31
    int lcq = threadIdx.x & 7;       // uint4 column 0..7 (8 bf16 each)

    for (int kc = 0; kc < D_; kc += 64) {
#pragma unroll
        for (int p = 0; p < 4; p++) {
            int row = lr + p * 32;
            *(uint4*)&sm[0][row * 72 + lcq * 8] =
                *(const uint4*)&Ag[(size_t)row * D_ + kc + lcq * 8];
            *(uint4*)&sm[1][row * 72 + lcq * 8] =
                *(const uint4*)&Bg[(size_t)row * D_ + kc + lcq * 8];
        }
        __syncthreads();
#pragma unroll
        for (int kk = 0; kk < 64; kk += 16) {
#pragma unroll
            for (int i = 0; i < 2; i++)
                wmma::load_matrix_sync(af[i], &sm[0][(wr * 32 + i * 16) * 72 + kk], 72);
#pragma unroll
            for (int j = 0; j < 4; j++)
                wmma::load_matrix_sync(bfr[j], &sm[1][(wc * 64 + j * 16) * 72 + kk], 72);
#pragma unroll
            for (int i = 0; i < 2; i++)
#pragma unroll
                for (int j = 0; j < 4; j++)
                    wmma::mma_sync(acc[i][j], af[i], bfr[j], acc[i][j]);
        }
        __syncthreads();
    }

    // Epilogue: alias staging smem as a 64x128 float tile, drain in anti-diagonal order.
    float* tile = (float*)&sm[0][0];   // 32KB < 36.9KB available
    for (int phase = 0; phase < 2; phase++) {
        if ((wr >> 1) == phase) {
            int lrr = (wr & 1) * 32;
#pragma unroll
            for (int i = 0; i < 2; i++)
#pragma unroll
                for (int j = 0; j < 4; j++)
                    wmma::store_matrix_sync(tile + (size_t)(lrr + i * 16) * 128 + wc * 64 + j * 16,
                                            acc[i][j], 128, wmma::mem_row_major);
        }
        __syncthreads();
        int rowoff = phase * 64;
        for (int e = threadIdx.x; e < 191 * 64; e += 256) {
            int dl = e >> 6;                          // local diag 0..190
            int t  = e & 63;
            int li = (dl > 127 ? dl - 127 : 0) + t;   // local row in half-tile
            int lj = dl - li;
            if (li < 64 && lj >= 0 && lj < 128) {
                int gi = I0 + rowoff + li;
                int gj = J0 + lj;
                g_theta[((size_t)b * NDIAG + (gi + gj)) * 1024 + gi] = tile[li * 128 + lj] * LOG2E;
            }
        }
        __syncthreads();
    }
}

// ---------------- 4) strip-parallel wavefront DP (log2 domain) ----------------
// 8 strips of 128 rows per batch; strips pipeline via g_bound/g_prog (release/acquire).
__global__ void __launch_bounds__(128) dp_kernel(float* __restrict__ out) {
    int s = blockIdx.x;               // strip
    int b = blockIdx.y;               // batch
    int t = threadIdx.x;              // 0..127, theta row i = r0 + t
    int r0 = s * SROWS;
    int i  = r0 + t;
    __shared__ float sbuf[2][136];

    sbuf[0][t + 1] = NEGW;
    sbuf[1][t + 1] = NEGW;
    if (t == 0) { sbuf[0][0] = NEGW; sbuf[1][0] = NEGW; }
    __syncthreads();

    const float A  = g_A[b];          // already * log2e
    const float A2 = A + A;

    // theta prefetch ring (4 deep), diag-major
    const float* pf = g_theta + (size_t)b * NDIAG * 1024 + (size_t)r0 * 1024 + i;
    float thb0 = pf[0];
    float thb1 = pf[1024];
    float thb2 = pf[2 * 1024];
    float thb3 = pf[3 * 1024];
    pf += 4 * 1024;

    // boundary plumbing
    const float* bsrc = &g_bound[b][(s == 0) ? 0 : (s - 1)][0];
    const int*   psrc = &g_prog[b][(s == 0) ? 0 : (s - 1)];
    float* bdst = &g_bound[b][s][0];
    int*   pdst = &g_prog[b][s];
    const int bend = (s > 0) ? (r0 + 1022) : -0x40000000;  // last diag with real producer value
    int cached = -1;

    float nb_prev, my_prev = NEGW;
    float bnd0 = NEGW, bnd1 = NEGW, bnd2 = NEGW, bnd3 = NEGW;
    if (t == 0) {
        if (s > 0) {
            int target = r0 + 2;
            while (cached < target) cached = ld_acq(psrc);
            nb_prev = __ldcg(bsrc + r0 - 2);
            bnd0 = __ldcg(bsrc + r0 - 1);
            bnd1 = __ldcg(bsrc + r0);
            bnd2 = __ldcg(bsrc + r0 + 1);
            bnd3 = __ldcg(bsrc + r0 + 2);
        } else {
            nb_prev = 0.0f;           // V[0][0]
        }
    } else {
        nb_prev = NEGW;
    }

    int cur = 0;
    const bool emit = (t == 127) && (s != STRIPS - 1);

#define DP_STEP(THV, BND, DD)                                              \
    {                                                                      \
        float nb = (t == 0) ? (BND) : sbuf[cur ^ 1][t];                    \
        float pre = *pf; pf += 1024;                                       \
        float bnew = NEGW;                                                 \
        if (t == 0 && (DD) + 3 <= bend) bnew = __ldcg(bsrc + (DD) + 3);    \
        float h  = fmaxf(nb, my_prev);                                     \
        float l  = fminf(nb, my_prev);                                     \
        float m  = fmaxf(h + A, nb_prev);                                  \
        float lo = fminf(l + A, nb_prev);                                  \
        float mid = ((h + l) + A2) + (nb_prev - m) - lo;                   \
        float sf = 1.0f + ex2f_(lo - m) + ex2f_(mid - m);                  \
        float val = ((THV) + m) + lg2f_(sf);                               \
        val = ((unsigned)((DD) - i) <= 1023u) ? val : NEGW;                \
        nb_prev = nb;                                                      \
        my_prev = val;                                                     \
        sbuf[cur][t + 1] = val;                                            \
        if (emit) {                                                        \
            bdst[(DD)] = val;                                              \
            if (((DD) & 7) == 7) st_rel(pdst, (DD));                       \
        }                                                                  \
        __syncthreads();                                                   \
        cur ^= 1;                                                          \
        (THV) = pre; (BND) = bnew;                                         \
    }

    // 1151 diagonals: 287 groups of 4 + 3 tail
    int d = r0;
    for (int g = 0; g < 287; g++, d += 4) {
        if (t == 0 && d + 3 <= bend) {
            int target = d + 6; if (target > bend) target = bend;
            while (cached < target) cached = ld_acq(psrc);
        }
        DP_STEP(thb0, bnd0, d)
        DP_STEP(thb1, bnd1, d + 1)
        DP_STEP(thb2, bnd2, d + 2)
        DP_STEP(thb3, bnd3, d + 3)
    }
    // tail: d = r0+1148 .. r0+1150 (boundary loads all beyond bend -> NEG, no spin)
    DP_STEP(thb0, bnd0, d)
    DP_STEP(thb1, bnd1, d + 1)
    DP_STEP(thb2, bnd2, d + 2)
#undef DP_STEP

    // ensure consumers can always pass their final spins
    if (emit) st_rel(pdst, 0x7FFFFFF0);

    // strip 7 thread 127's last value (d = r0+1150 = 2046) is V[N][M] in log2 domain
    if (s == STRIPS - 1 && t == 127) out[b] = my_prev * LN2;
}

// ---------------- launch ----------------
extern "C" void kernel_launch(void* const* d_in, const int* in_sizes, int n_in,
                              void* d_out, int out_size) {
    (void)in_sizes; (void)n_in; (void)out_size;
    const float* zx = (const float*)d_in[0];
    const float* zy = (const float*)d_in[1];
    const float* gw = (const float*)d_in[2];
    const float* gb = (const float*)d_in[3];
    float* out = (float*)d_out;

    reset_kernel<<<1, 128>>>();
    convert_kernel<<<1024, 256>>>(zx, zy);
    gap_kernel<<<B_, 1024>>>(zx, zy, gw, gb);
    gemm_kernel<<<dim3(8, 8, B_), 256>>>();
    dp_kernel<<<dim3(STRIPS, B_), 128>>>(out);
}

// round 4
// speedup vs baseline: 2.0499x; 1.3515x over previous
#include <cuda_runtime.h>
#include <cuda_bf16.h>
#include <mma.h>

using namespace nvcuda;

#define B_    16
#define N_    1024
#define M_    1024
#define D_    512
#define NDIAG 2047            // theta anti-diagonals: i+j in [0, 2046]
#define LOG2E 1.4426950408889634f
#define LN2   0.6931471805599453f
#define NEGW  -1.0e9f
#define STRIPS 8
#define SROWS  128

// ---------------- device scratch (static globals: no allocation) ----------------
__device__ __nv_bfloat16 g_zx[(size_t)B_ * N_ * D_];
__device__ __nv_bfloat16 g_zy[(size_t)B_ * M_ * D_];
// diag-major: [b][d][i], ~134MB, +8 diagonals of pad so prefetch never reads OOB
__device__ float g_theta[(size_t)B_ * NDIAG * 1024 + 8 * 1024];
__device__ float g_A[B_];
__device__ float g_gpart[B_][8];
__device__ float g_bound[B_][STRIPS][2048];   // strip boundary V-row values by global diag
__device__ int   g_prog[B_][STRIPS];          // release/acquire progress per strip

// ---------------- fast MUFU intrinsics ----------------
__device__ __forceinline__ float ex2f_(float x) {
    float y; asm("ex2.approx.ftz.f32 %0, %1;" : "=f"(y) : "f"(x)); return y;
}
__device__ __forceinline__ float lg2f_(float x) {
    float y; asm("lg2.approx.ftz.f32 %0, %1;" : "=f"(y) : "f"(x)); return y;
}
__device__ __forceinline__ int ld_acq(const int* p) {
    int v; asm volatile("ld.acquire.gpu.global.b32 %0, [%1];" : "=r"(v) : "l"(p)); return v;
}
__device__ __forceinline__ void st_rel(int* p, int v) {
    asm volatile("st.release.gpu.global.b32 [%0], %1;" :: "l"(p), "r"(v));
}

// ---------------- 0) reset progress flags (graph-replay safe) ----------------
__global__ void reset_kernel() {
    int i = threadIdx.x;
    if (i < B_ * STRIPS) ((int*)g_prog)[i] = -1;
}

// ---------------- 1) fp32 -> bf16 conversion ----------------
__global__ void convert_kernel(const float* __restrict__ x, const float* __restrict__ y) {
    int i = blockIdx.x * blockDim.x + threadIdx.x;
    int st = gridDim.x * blockDim.x;
    const int n = B_ * N_ * D_;
    for (; i < n; i += st) {
        g_zx[i] = __float2bfloat16(x[i]);
        g_zy[i] = __float2bfloat16(y[i]);
    }
}

// ---------------- 2) gap score A[b]: two-stage deterministic reduce ----------------
__global__ void __launch_bounds__(512) gap_part(const float* __restrict__ zx,
                                                const float* __restrict__ zy,
                                                const float* __restrict__ gw) {
    int blk = blockIdx.x;           // row block 0..7 (128 rows)
    int b   = blockIdx.y;
    int c   = threadIdx.x;          // feature 0..511
    const float* px = zx + ((size_t)b * N_ + (size_t)blk * 128) * D_ + c;
    const float* py = zy + ((size_t)b * M_ + (size_t)blk * 128) * D_ + c;
    float sx = 0.f, sy = 0.f;
#pragma unroll 4
    for (int r = 0; r < 128; r++) {
        sx += px[(size_t)r * D_];
        sy += py[(size_t)r * D_];
    }
    float v = sx * (1.0f / N_) * gw[c] + sy * (1.0f / M_) * gw[512 + c];
    __shared__ float red[512];
    red[c] = v;
    __syncthreads();
    for (int s = 256; s > 0; s >>= 1) {
        if (c < s) red[c] += red[c + s];
        __syncthreads();
    }
    if (c == 0) g_gpart[b][blk] = red[0];
}

__global__ void gap_final(const float* __restrict__ gb) {
    int b = threadIdx.x;
    if (b < B_) {
        float s = 0.f;
#pragma unroll
        for (int k = 0; k < 8; k++) s += g_gpart[b][k];
        g_A[b] = (s + gb[0]) * LOG2E;   // log2-domain gap
    }
}

// ---------------- 3) GEMM theta = zx @ zy^T, bf16 WMMA with smem staging ----------------
// block tile 128x128, 8 warps (4 row x 2 col), each warp 32x64. K staged in 64-chunks.
__global__ void __launch_bounds__(256) gemm_kernel() {
    __shared__ __align__(16) __nv_bfloat16 sm[2][128 * 72];   // A | B, 36.9KB (pad 72)

    int b  = blockIdx.z;
    int I0 = blockIdx.y * 128;
    int J0 = blockIdx.x * 128;
    const __nv_bfloat16* Ag = g_zx + ((size_t)b * N_ + I0) * D_;
    const __nv_bfloat16* Bg = g_zy + ((size_t)b * M_ + J0) * D_;

    int warpId = threadIdx.x >> 5;
    int wr = warpId & 3;       // 0..3 (rows of 32)
    int wc = warpId >> 2;      // 0..1 (cols of 64)

    wmma::fragment<wmma::accumulator, 16, 16, 16, float> acc[2][4];
#pragma unroll
    for (int i = 0; i < 2; i++)
#pragma unroll
        for (int j = 0; j < 4; j++) wmma::fill_fragment(acc[i][j], 0.0f);

    wmma::fragment<wmma::matrix_a, 16, 16, 16, __nv_bfloat16, wmma::row_major> af[2];
    wmma::fragment<wmma::matrix_b, 16, 16, 16, __nv_bfloat16, wmma::col_major> bfr[4];

    int lr  = threadIdx.x >> 3;      // 0..31
    int lcq = threadIdx.x & 7;       // uint4 column 0..7 (8 bf16 each)

    for (int kc = 0; kc < D_; kc += 64) {
#pragma unroll
        for (int p = 0; p < 4; p++) {
            int row = lr + p * 32;
            *(uint4*)&sm[0][row * 72 + lcq * 8] =
                *(const uint4*)&Ag[(size_t)row * D_ + kc + lcq * 8];
            *(uint4*)&sm[1][row * 72 + lcq * 8] =
                *(const uint4*)&Bg[(size_t)row * D_ + kc + lcq * 8];
        }
        __syncthreads();
#pragma unroll
        for (int kk = 0; kk < 64; kk += 16) {
#pragma unroll
            for (int i = 0; i < 2; i++)
                wmma::load_matrix_sync(af[i], &sm[0][(wr * 32 + i * 16) * 72 + kk], 72);
#pragma unroll
            for (int j = 0; j < 4; j++)
                wmma::load_matrix_sync(bfr[j], &sm[1][(wc * 64 + j * 16) * 72 + kk], 72);
#pragma unroll
            for (int i = 0; i < 2; i++)
#pragma unroll
                for (int j = 0; j < 4; j++)
                    wmma::mma_sync(acc[i][j], af[i], bfr[j], acc[i][j]);
        }
        __syncthreads();
    }

    // Epilogue: alias staging smem as a 64x128 float tile, drain in anti-diagonal order.
    float* tile = (float*)&sm[0][0];   // 32KB < 36.9KB available
    for (int phase = 0; phase < 2; phase++) {
        if ((wr >> 1) == phase) {
            int lrr = (wr & 1) * 32;
#pragma unroll
            for (int i = 0; i < 2; i++)
#pragma unroll
                for (int j = 0; j < 4; j++)
                    wmma::store_matrix_sync(tile + (size_t)(lrr + i * 16) * 128 + wc * 64 + j * 16,
                                            acc[i][j], 128, wmma::mem_row_major);
        }
        __syncthreads();
        int rowoff = phase * 64;
        for (int e = threadIdx.x; e < 191 * 64; e += 256) {
            int dl = e >> 6;                          // local diag 0..190
            int t  = e & 63;
            int li = (dl > 127 ? dl - 127 : 0) + t;   // local row in half-tile
            int lj = dl - li;
            if (li < 64 && lj >= 0 && lj < 128) {
                int gi = I0 + rowoff + li;
                int gj = J0 + lj;
                g_theta[((size_t)b * NDIAG + (gi + gj)) * 1024 + gi] = tile[li * 128 + lj] * LOG2E;
            }
        }
        __syncthreads();
    }
}

// ---------------- 4) strip-parallel wavefront DP, chunked boundary handoff ----------------
// 8 strips x 128 rows per batch. Boundary values move in 32-diag chunks: one coalesced
// 128B load + one acquire poll per chunk, double-buffered in smem (latency amortized).
__global__ void __launch_bounds__(128) dp_kernel(float* __restrict__ out) {
    int s = blockIdx.x;               // strip
    int b = blockIdx.y;               // batch
    int t = threadIdx.x;              // 0..127, theta row i = r0 + t
    int r0 = s * SROWS;
    int i  = r0 + t;
    __shared__ float sbuf[2][136];
    __shared__ float bq[2][32];       // boundary chunk double buffer

    sbuf[0][t + 1] = NEGW;
    sbuf[1][t + 1] = NEGW;
    if (t == 0) { sbuf[0][0] = NEGW; sbuf[1][0] = NEGW; }

    const float A  = g_A[b];          // already * log2e
    const float A2 = A + A;

    // theta prefetch ring (4 deep), diag-major
    const float* pf = g_theta + (size_t)b * NDIAG * 1024 + (size_t)r0 * 1024 + i;
    float th0 = pf[0];
    float th1 = pf[1024];
    float th2 = pf[2 * 1024];
    float th3 = pf[3 * 1024];
    pf += 4 * 1024;

    const float* bsrc = &g_bound[b][(s == 0) ? 0 : (s - 1)][0];
    const int*   psrc = &g_prog[b][(s == 0) ? 0 : (s - 1)];
    float* bdst = &g_bound[b][s][0];
    int*   pdst = &g_prog[b][s];
    const int bend = (s > 0) ? (r0 + 1022) : -0x40000000;  // last real producer diag
    int cached = -1;

    // prologue: warp 0 loads chunk 0 (boundary indices r0-1 .. r0+30)
    if (t < 32) {
        int base = r0 - 1;
        float v = NEGW;
        if (base <= bend) {
            int target = min(base + 31, bend);
            if (t == 0) { while (cached < target) cached = ld_acq(psrc); }
            __syncwarp();
            int idx = base + t;
            if (idx <= bend) v = __ldcg(bsrc + idx);
        }
        bq[0][t] = v;
    }
    float nb_prev;
    if (t == 0) nb_prev = (s > 0) ? __ldcg(bsrc + r0 - 2) : 0.0f;
    else        nb_prev = NEGW;
    float my_prev = NEGW;
    int cur = 0;
    __syncthreads();

    const bool emit = (t == 127) && (s != STRIPS - 1);
    int p = 0;                         // step index (diag = r0 + p)

#define DP_STEP(THV, CB, OFF)                                              \
    {                                                                      \
        float nb = (t == 0) ? bq[CB][OFF] : sbuf[cur ^ 1][t];              \
        float pre = *pf; pf += 1024;                                       \
        float h  = fmaxf(nb, my_prev);                                     \
        float l  = fminf(nb, my_prev);                                     \
        float m  = fmaxf(h + A, nb_prev);                                  \
        float lo = fminf(l + A, nb_prev);                                  \
        float mid = ((h + l) + A2) + (nb_prev - m) - lo;                   \
        float sf = 1.0f + ex2f_(lo - m) + ex2f_(mid - m);                  \
        int dd = r0 + p;                                                   \
        float val = ((THV) + m) + lg2f_(sf);                               \
        val = ((unsigned)(dd - i) <= 1023u) ? val : NEGW;                  \
        nb_prev = nb;                                                      \
        my_prev = val;                                                     \
        sbuf[cur][t + 1] = val;                                            \
        if (emit) __stcg(bdst + dd, val);                                  \
        __syncthreads();                                                   \
        cur ^= 1; (THV) = pre; p++;                                        \
    }

    // 35 full chunks of 32 steps (0..1119), prefetching chunk c+1 each iteration
    for (int c = 0; c < 35; c++) {
        if (t < 32) {
            int base = r0 + (c + 1) * 32 - 1;
            float v = NEGW;
            if (base <= bend) {
                int target = min(base + 31, bend);
                if (t == 0) { while (cached < target) cached = ld_acq(psrc); }
                __syncwarp();
                int idx = base + t;
                if (idx <= bend) v = __ldcg(bsrc + idx);
            }
            bq[(c + 1) & 1][t] = v;
        }
        int cb = c & 1;
#pragma unroll
        for (int g = 0; g < 8; g++) {
            DP_STEP(th0, cb, g * 4 + 0)
            DP_STEP(th1, cb, g * 4 + 1)
            DP_STEP(th2, cb, g * 4 + 2)
            DP_STEP(th3, cb, g * 4 + 3)
        }
        if (emit) st_rel(pdst, r0 + c * 32 + 31);
    }
    // tail chunk 35: 31 steps (1120..1150), data already in bq[1]
    {
        const int cb = 1;
#pragma unroll
        for (int g = 0; g < 7; g++) {
            DP_STEP(th0, cb, g * 4 + 0)
            DP_STEP(th1, cb, g * 4 + 1)
            DP_STEP(th2, cb, g * 4 + 2)
            DP_STEP(th3, cb, g * 4 + 3)
        }
        DP_STEP(th0, cb, 28)
        DP_STEP(th1, cb, 29)
        DP_STEP(th2, cb, 30)
    }
#undef DP_STEP

    if (emit) st_rel(pdst, 0x7FFFFFF0);   // final release: covers all remaining diags

    // strip 7 thread 127's last value (diag 2046) is V[N][M] in log2 domain
    if (s == STRIPS - 1 && t == 127) out[b] = my_prev * LN2;
}

// ---------------- launch ----------------
extern "C" void kernel_launch(void* const* d_in, const int* in_sizes, int n_in,
                              void* d_out, int out_size) {
    (void)in_sizes; (void)n_in; (void)out_size;
    const float* zx = (const float*)d_in[0];
    const float* zy = (const float*)d_in[1];
    const float* gw = (const float*)d_in[2];
    const float* gb = (const float*)d_in[3];
    float* out = (float*)d_out;

    reset_kernel<<<1, 128>>>();
    convert_kernel<<<1024, 256>>>(zx, zy);
    gap_part<<<dim3(8, B_), 512>>>(zx, zy, gw);
    gap_final<<<1, 32>>>(gb);
    gemm_kernel<<<dim3(8, 8, B_), 256>>>();
    dp_kernel<<<dim3(STRIPS, B_), 128>>>(out);
}